// round 6
// baseline (speedup 1.0000x reference)
#include <cuda_runtime.h>
#include <math.h>

#define H 1024
#define L 4096
#define V 29
#define NB 444            // 3 blocks per SM x 148 SMs, co-resident
#define NT 512
#define WPB 16
#define WTOT (NB * WPB)   // 7104 warps

// ---------------- scratch (device globals) ----------------------------------
__device__ float g_smax[NB];           // per-block score slice max
__device__ float g_ssum[NB];           // per-block expsum under local max
__device__ float g_hh[4 * H];          // W_hh @ h0
__device__ float g_xe[H];              // comb_W[:, :H] @ emb
__device__ float4 g_attn4[H / 4];      // attn_applied (16B aligned for red.v4)
__device__ float g_xp[4 * H];          // comb attn-half partials [row*4+q]
__device__ float g_gp[8 * H];          // W_ih partials [row*2+half]
__device__ unsigned g_cnt = 0;
__device__ volatile unsigned g_flag = 0;

// ---------------- helpers ----------------------------------------------------
__device__ __forceinline__ float warp_sum(float v) {
#pragma unroll
    for (int o = 16; o; o >>= 1) v += __shfl_xor_sync(0xffffffffu, v, o);
    return v;
}
__device__ __forceinline__ float warp_max(float v) {
#pragma unroll
    for (int o = 16; o; o >>= 1) v = fmaxf(v, __shfl_xor_sync(0xffffffffu, v, o));
    return v;
}
__device__ __forceinline__ float sigmoidf_(float x) { return 1.0f / (1.0f + expf(-x)); }
__device__ __forceinline__ float dot4(float4 a, float4 b) {
    return a.x * b.x + a.y * b.y + a.z * b.z + a.w * b.w;
}
// 1024-elt dot, v in shared
__device__ __forceinline__ float dot1024(const float4* __restrict__ w,
                                         const float4* __restrict__ v, int lane) {
    float a0 = 0.f, a1 = 0.f;
#pragma unroll
    for (int k = 0; k < 8; k += 2) {
        a0 += dot4(w[lane + 32 * k],       v[lane + 32 * k]);
        a1 += dot4(w[lane + 32 * (k + 1)], v[lane + 32 * (k + 1)]);
    }
    return a0 + a1;
}
// 512-elt dot
__device__ __forceinline__ float dot512(const float4* __restrict__ w,
                                        const float4* __restrict__ v, int lane) {
    float a0 = dot4(w[lane],      v[lane])      + dot4(w[lane + 64], v[lane + 64]);
    float a1 = dot4(w[lane + 32], v[lane + 32]) + dot4(w[lane + 96], v[lane + 96]);
    return a0 + a1;
}

__device__ __forceinline__ void redv4(float4* addr, float4 v) {
    asm volatile("red.global.add.v4.f32 [%0], {%1, %2, %3, %4};"
                 :: "l"(addr), "f"(v.x), "f"(v.y), "f"(v.z), "f"(v.w) : "memory");
}

__device__ __forceinline__ void grid_barrier(unsigned sense) {
    __syncthreads();
    if (threadIdx.x == 0) {
        __threadfence();
        unsigned old = atomicAdd(&g_cnt, 1u);
        if (old == NB - 1) {
            g_cnt = 0;
            __threadfence();
            g_flag = sense;
        } else {
            while (g_flag != sense) { __nanosleep(32); }
        }
        __threadfence();
    }
    __syncthreads();
}

// ---------------- the whole decoder step in one kernel -----------------------
__global__ void __launch_bounds__(NT, 3)
k_decoder(const int* __restrict__ tok,
          const float* __restrict__ h0,
          const float* __restrict__ c0,
          const float* __restrict__ enc,
          const float* __restrict__ emb,
          const float* __restrict__ attn_W,
          const float* __restrict__ attn_b,
          const float* __restrict__ comb_W,
          const float* __restrict__ comb_b,
          const float* __restrict__ W_ih,
          const float* __restrict__ W_hh,
          const float* __restrict__ b_ih,
          const float* __restrict__ b_hh,
          const float* __restrict__ out_W,
          const float* __restrict__ out_b,
          float* __restrict__ out) {
    __shared__ float s[2 * H];       // [emb|h0] -> [attn] -> [x] -> [h]
    __shared__ float wscp[20];       // own-score half partials
    __shared__ float s_sc[10];       // own scores
    __shared__ float wts[10];        // own softmax weights
    __shared__ float bM, bS;
    __shared__ float z[32];

    const int t = threadIdx.x;
    const int warp = t >> 5, lane = t & 31;
    const int b = blockIdx.x;
    const int wg = b * WPB + warp;
    const int nr = 9 + (b < (L - 9 * NB) ? 1 : 0);   // rows: b, b+NB, ...
    float* attn_out = out + V + 2 * H;               // [lp | h | c | attn_w]
    float* g_attn = (float*)g_attn4;

    // ===== Phase A: own scores + stats, W_hh@h0, comb_W-emb-half ============
    {
        const float* erow = emb + (size_t)tok[0] * H;
#pragma unroll
        for (int k = 0; k < 2; k++) {
            int i = t + k * NT;
            s[i] = erow[i];
            s[H + i] = h0[i];
            if (b == 0) g_attn[i] = 0.0f;
        }
        __syncthreads();

        // own score chunks: j<nr -> half0 (emb), else half1 (h0)
        for (int j = warp; j < 2 * nr; j += WPB) {
            int half = (j >= nr);
            int r = b + (half ? j - nr : j) * NB;
            const float4* wp = (const float4*)(attn_W + (size_t)r * (2 * H) + half * H);
            const float4* vp = (const float4*)(s + half * H);
            float acc = dot1024(wp, vp, lane);
            acc = warp_sum(acc);
            if (lane == 0) wscp[j] = acc;
        }
        // shared units: 4096 hh rows + 1024 comb-emb rows
        if (wg < 5120) {
            if (wg < 4096) {
                const float4* wp = (const float4*)(W_hh + (size_t)wg * H);
                float acc = dot1024(wp, (const float4*)(s + H), lane);
                acc = warp_sum(acc);
                if (lane == 0) g_hh[wg] = acc;
            } else {
                int r = wg - 4096;
                const float4* wp = (const float4*)(comb_W + (size_t)r * (2 * H));
                float acc = dot1024(wp, (const float4*)s, lane);
                acc = warp_sum(acc);
                if (lane == 0) g_xe[r] = acc;
            }
        }
        __syncthreads();

        if (t < nr) s_sc[t] = wscp[t] + wscp[t + nr] + attn_b[b + t * NB];
        __syncthreads();
        if (warp == 0) {
            float v = (lane < nr) ? s_sc[lane] : -1e30f;
            float lm = warp_max(v);
            float e = (lane < nr) ? expf(s_sc[lane] - lm) : 0.0f;
            float ls = warp_sum(e);
            if (lane == 0) { g_smax[b] = lm; g_ssum[b] = ls; }
        }
    }
    grid_barrier(1);

    // ===== Phase B: combine stats, weights, weighted encoder sum ============
    {
        if (warp == 0) {
            float m = -1e30f;
            for (int i = lane; i < NB; i += 32) m = fmaxf(m, g_smax[i]);
            m = warp_max(m);
            float ss = 0.0f;
            for (int i = lane; i < NB; i += 32) ss += g_ssum[i] * expf(g_smax[i] - m);
            ss = warp_sum(ss);
            if (lane == 0) { bM = m; bS = 1.0f / ss; }
        }
        __syncthreads();
        if (t < nr) {
            float w = expf(s_sc[t] - bM) * bS;
            wts[t] = w;
            attn_out[b + t * NB] = w;
        }
        __syncthreads();

        const int grp = t >> 8, col = t & 255;   // 2 row-groups x 256 float4 cols
        float4 acc = make_float4(0.f, 0.f, 0.f, 0.f);
        for (int i = grp; i < nr; i += 2) {
            const float4* ef = (const float4*)(enc + (size_t)(b + i * NB) * H);
            float4 v = ef[col];
            float w = wts[i];
            acc.x += w * v.x; acc.y += w * v.y; acc.z += w * v.z; acc.w += w * v.w;
        }
        float4* sb = (float4*)s;
        if (grp == 1) sb[col] = acc;
        __syncthreads();
        if (grp == 0) {
            float4 o = sb[col];
            acc.x += o.x; acc.y += o.y; acc.z += o.z; acc.w += o.w;
            redv4(&g_attn4[col], acc);
        }
    }
    grid_barrier(0);

    // ===== Phase C: comb attn-half, 4096 quarter-row chunks =================
    {
        s[t] = g_attn[t];
        s[t + NT] = g_attn[t + NT];
        __syncthreads();
        if (wg < 4 * H) {
            int row = wg >> 2, q = wg & 3;
            const float4* wp = (const float4*)(comb_W + (size_t)row * (2 * H) + H + q * 256);
            const float4* vp = (const float4*)(s + q * 256);
            float a = dot4(wp[lane], vp[lane]) + dot4(wp[lane + 32], vp[lane + 32]);
            a = warp_sum(a);
            if (lane == 0) g_xp[wg] = a;
        }
    }
    grid_barrier(1);

    // ===== Phase D: x build + W_ih half-row chunks ==========================
    {
        const float4* xpf = (const float4*)g_xp;
#pragma unroll
        for (int k = 0; k < 2; k++) {
            int i = t + k * NT;
            float4 p = xpf[i];
            s[i] = fmaxf(g_xe[i] + p.x + p.y + p.z + p.w + comb_b[i], 0.0f);
        }
        __syncthreads();
        for (int u = wg; u < 8 * H; u += WTOT) {
            int row = u >> 1, half = u & 1;
            const float4* wp = (const float4*)(W_ih + (size_t)row * H + half * 512);
            const float4* vp = (const float4*)(s + half * 512);
            float a = dot512(wp, vp, lane);
            a = warp_sum(a);
            if (lane == 0) g_gp[u] = a;
        }
    }
    grid_barrier(0);

    // ===== Phase E: LSTM pointwise + out proj + log_softmax (block 0) =======
    if (b == 0) {
        const float2* gp = (const float2*)g_gp;
#pragma unroll
        for (int k = 0; k < 2; k++) {
            int i = t + k * NT;
            float2 pi = gp[i];
            float2 pf = gp[H + i];
            float2 pg = gp[2 * H + i];
            float2 po = gp[3 * H + i];
            float ig = pi.x + pi.y + g_hh[i]         + b_ih[i]         + b_hh[i];
            float fg = pf.x + pf.y + g_hh[H + i]     + b_ih[H + i]     + b_hh[H + i];
            float gg = pg.x + pg.y + g_hh[2 * H + i] + b_ih[2 * H + i] + b_hh[2 * H + i];
            float og = po.x + po.y + g_hh[3 * H + i] + b_ih[3 * H + i] + b_hh[3 * H + i];
            float c = sigmoidf_(fg) * c0[i] + sigmoidf_(ig) * tanhf(gg);
            float h = sigmoidf_(og) * tanhf(c);
            out[V + i] = h;
            out[V + H + i] = c;
            s[i] = h;
        }
        __syncthreads();

        const float4* hv = (const float4*)s;
        for (int row = warp; row < V; row += WPB) {
            const float4* wr = (const float4*)(out_W + (size_t)row * H);
            float acc = dot1024(wr, hv, lane);
            acc = warp_sum(acc);
            if (lane == 0) z[row] = acc + out_b[row];
        }
        __syncthreads();

        if (t == 0) {
            float m = -1e30f;
            for (int r = 0; r < V; r++) m = fmaxf(m, z[r]);
            float ssum = 0.0f;
            for (int r = 0; r < V; r++) ssum += expf(z[r] - m);
            float ls = m + logf(ssum);
            for (int r = 0; r < V; r++) out[r] = z[r] - ls;
        }
    }
}

// ---------------- launch ------------------------------------------------------
extern "C" void kernel_launch(void* const* d_in, const int* in_sizes, int n_in,
                              void* d_out, int out_size) {
    const int*   tok    = (const int*)  d_in[0];
    const float* h0     = (const float*)d_in[1];
    const float* c0     = (const float*)d_in[2];
    const float* enc    = (const float*)d_in[3];
    const float* emb    = (const float*)d_in[4];
    const float* attn_W = (const float*)d_in[5];
    const float* attn_b = (const float*)d_in[6];
    const float* comb_W = (const float*)d_in[7];
    const float* comb_b = (const float*)d_in[8];
    const float* W_ih   = (const float*)d_in[9];
    const float* W_hh   = (const float*)d_in[10];
    const float* b_ih   = (const float*)d_in[11];
    const float* b_hh   = (const float*)d_in[12];
    const float* out_W  = (const float*)d_in[13];
    const float* out_b  = (const float*)d_in[14];
    float* out = (float*)d_out;

    k_decoder<<<NB, NT>>>(tok, h0, c0, enc, emb, attn_W, attn_b,
                          comb_W, comb_b, W_ih, W_hh, b_ih, b_hh,
                          out_W, out_b, out);
}

// round 8
// speedup vs baseline: 1.0948x; 1.0948x over previous
#include <cuda_runtime.h>
#include <math.h>

#define H 1024
#define L 4096
#define V 29
#define NB 148
#define NT 1024
#define DEPTH 5
#define SLOT_FLOATS 8192                       // 32 KB per stage
#define RING_FLOATS (DEPTH * SLOT_FLOATS)
#define SMEM_FLOATS (2 * H + RING_FLOATS)
#define SMEM_BYTES (SMEM_FLOATS * 4)           // 168 KB dynamic

// ---------------- scratch (device globals) ----------------------------------
__device__ float g_scores[L];          // scores incl. bias
__device__ float g_hh[4 * H];
__device__ float g_attn[H];
__device__ float g_x[H];
__device__ float g_gates[4 * H];
__device__ unsigned g_cnt = 0;
__device__ volatile unsigned g_flag = 0;

// ---------------- helpers ----------------------------------------------------
__device__ __forceinline__ float warp_sum(float v) {
#pragma unroll
    for (int o = 16; o; o >>= 1) v += __shfl_xor_sync(0xffffffffu, v, o);
    return v;
}
__device__ __forceinline__ float warp_max(float v) {
#pragma unroll
    for (int o = 16; o; o >>= 1) v = fmaxf(v, __shfl_xor_sync(0xffffffffu, v, o));
    return v;
}
__device__ __forceinline__ float sigmoidf_(float x) { return 1.0f / (1.0f + expf(-x)); }
__device__ __forceinline__ float dot4(float4 a, float4 b) {
    return a.x * b.x + a.y * b.y + a.z * b.z + a.w * b.w;
}

__device__ __forceinline__ void grid_barrier(unsigned sense) {
    __syncthreads();
    if (threadIdx.x == 0) {
        __threadfence();
        unsigned old = atomicAdd(&g_cnt, 1u);
        if (old == NB - 1) {
            g_cnt = 0;
            __threadfence();
            g_flag = sense;
        } else {
            while (g_flag != sense) { __nanosleep(32); }
        }
        __threadfence();
    }
    __syncthreads();
}

// ---------------- cp.async plumbing ------------------------------------------
__device__ __forceinline__ unsigned smem_u32(const void* p) {
    return (unsigned)__cvta_generic_to_shared(p);
}
__device__ __forceinline__ void cp16(unsigned dst, const float* src) {
    asm volatile("cp.async.cg.shared.global [%0], [%1], 16;"
                 :: "r"(dst), "l"(src) : "memory");
}
__device__ __forceinline__ void cp_commit() {
    asm volatile("cp.async.commit_group;" ::: "memory");
}
template <int N> __device__ __forceinline__ void cp_wait() {
    asm volatile("cp.async.wait_group %0;" :: "n"(N) : "memory");
}
// copy `units` 16B-chunks (<=2048) from g into slot; every thread commits.
// INVARIANT: every call adds exactly ONE group per thread.
__device__ __forceinline__ void issue_stage(unsigned slot, const float* g, int units) {
    int t = threadIdx.x;
    if (t < units) cp16(slot + t * 16, g + t * 4);
    int t2 = t + 1024;
    if (t2 < units) cp16(slot + t2 * 16, g + t2 * 4);
    cp_commit();
}

// ---------------- dot-tile mapping: phase A -----------------------------------
// tiles 0..1023: attn_W (4 rows x 2048); tiles 1024..1535: W_hh (8 rows x 1024)
__device__ __forceinline__ const float* tileA(int tile, const float* attn_W,
                                              const float* W_hh, int& RL,
                                              int& row0, int& mat, int& vecoff) {
    if (tile < 1024) { RL = 2048; mat = 0; row0 = tile * 4; vecoff = 0;
                       return attn_W + (size_t)tile * SLOT_FLOATS; }
    int u = tile - 1024;
    RL = 1024; mat = 1; row0 = u * 8; vecoff = 1024;
    return W_hh + (size_t)u * SLOT_FLOATS;
}

// consume one 32KB dot stage; mat: 0=scores 1=hh 2=comb 3=ih
__device__ __forceinline__ void consume_dot(const float4* slot, const float4* vec,
                                            int RL, int row0, int mat,
                                            const float* attn_b, const float* comb_b,
                                            const float* b_ih, const float* b_hh,
                                            float* s_part) {
    int t = threadIdx.x, warp = t >> 5, lane = t & 31;
    int R = SLOT_FLOATS / RL;         // 4 or 8 rows per stage
    int wpr = 32 / R;                 // warps per row: 8 or 4
    int row = warp / wpr, part = warp - row * wpr;
    int fo = (row * RL + part * 256) >> 2;
    int vo = (part * 256) >> 2;
    float4 w0 = slot[fo + lane],      w1 = slot[fo + 32 + lane];
    float4 v0 = vec[vo + lane],       v1 = vec[vo + 32 + lane];
    float p = dot4(w0, v0) + dot4(w1, v1);
    p = warp_sum(p);
    if (lane == 0) s_part[warp] = p;
    __syncthreads();
    if (warp < R) {
        float v = (lane < wpr) ? s_part[warp * wpr + lane] : 0.0f;
        v = warp_sum(v);
        if (lane == 0) {
            int gr = row0 + warp;
            if      (mat == 0) g_scores[gr] = v + attn_b[gr];
            else if (mat == 1) g_hh[gr] = v;
            else if (mat == 2) g_x[gr] = fmaxf(v + comb_b[gr], 0.0f);
            else               g_gates[gr] = v + g_hh[gr] + b_ih[gr] + b_hh[gr];
        }
    }
}

// ---------------- the whole decoder step in one kernel -----------------------
__global__ void __launch_bounds__(NT, 1)
k_decoder(const int* __restrict__ tok,
          const float* __restrict__ h0,
          const float* __restrict__ c0,
          const float* __restrict__ enc,
          const float* __restrict__ emb,
          const float* __restrict__ attn_W,
          const float* __restrict__ attn_b,
          const float* __restrict__ comb_W,
          const float* __restrict__ comb_b,
          const float* __restrict__ W_ih,
          const float* __restrict__ W_hh,
          const float* __restrict__ b_ih,
          const float* __restrict__ b_hh,
          const float* __restrict__ out_W,
          const float* __restrict__ out_b,
          float* __restrict__ out) {
    extern __shared__ float s_dyn[];
    float* s_vec = s_dyn;                      // 2048 floats
    float* ring  = s_dyn + 2 * H;              // DEPTH x 8192 floats
    __shared__ float s_part[32];
    __shared__ float red[32];
    __shared__ float bcast;
    __shared__ float s_wts[28];
    __shared__ float z[32];

    const int t = threadIdx.x;
    const int warp = t >> 5, lane = t & 31;
    const int b = blockIdx.x;
    float* attn_out = out + V + 2 * H;         // [lp | h | c | attn_w]

    unsigned slot_addr[DEPTH];
#pragma unroll
    for (int i = 0; i < DEPTH; i++) slot_addr[i] = smem_u32(ring + i * SLOT_FLOATS);

    // ===== Phase A: attn scores + W_hh@h0, cp.async pipelined ===============
    {
        const float* erow = emb + (size_t)tok[0] * H;
        s_vec[t] = erow[t];
        s_vec[H + t] = h0[t];
        if (b == 0) g_attn[t] = 0.0f;

        const int tb = (b * 1536) / NB, te = ((b + 1) * 1536) / NB;
        const int n = te - tb;
        int RL, row0, mat, vecoff;
        // prologue: ALWAYS exactly DEPTH groups (pad with empty commits)
#pragma unroll
        for (int k = 0; k < DEPTH; k++) {
            if (k < n) {
                const float* src = tileA(tb + k, attn_W, W_hh, RL, row0, mat, vecoff);
                issue_stage(slot_addr[k], src, 2048);
            } else {
                cp_commit();
            }
        }
        for (int k = 0; k < n; k++) {
            cp_wait<DEPTH - 1>();   // exactly DEPTH outstanding -> drains stage k
            __syncthreads();
            tileA(tb + k, attn_W, W_hh, RL, row0, mat, vecoff);
            consume_dot((const float4*)(ring + (k % DEPTH) * SLOT_FLOATS),
                        (const float4*)(s_vec + vecoff), RL, row0, mat,
                        attn_b, comb_b, b_ih, b_hh, s_part);
            __syncthreads();
            if (k + DEPTH < n) {
                const float* src = tileA(tb + k + DEPTH, attn_W, W_hh, RL, row0, mat, vecoff);
                issue_stage(slot_addr[k % DEPTH], src, 2048);
            } else {
                cp_commit();        // keep exactly DEPTH outstanding
            }
        }
        cp_wait<0>();
    }
    grid_barrier(1);

    // ===== Phase B: softmax (block-redundant) + pipelined weighted enc sum ==
    {
        float sc[4];
        float m = -1e30f;
#pragma unroll
        for (int k = 0; k < 4; k++) {
            sc[k] = g_scores[t + k * 1024];
            m = fmaxf(m, sc[k]);
        }
        m = warp_max(m);
        if (lane == 0) red[warp] = m;
        __syncthreads();
        if (warp == 0) {
            float x = red[lane];
            x = warp_max(x);
            if (lane == 0) bcast = x;
        }
        __syncthreads();
        const float M = bcast;

        float sum = 0.0f;
#pragma unroll
        for (int k = 0; k < 4; k++) sum += expf(sc[k] - M);
        sum = warp_sum(sum);
        __syncthreads();
        if (lane == 0) red[warp] = sum;
        __syncthreads();
        if (warp == 0) {
            float x = red[lane];
            x = warp_sum(x);
            if (lane == 0) bcast = x;
        }
        __syncthreads();
        const float invS = 1.0f / bcast;

        const int rb0 = b * 28;
        const int nrows = (rb0 < L) ? ((L - rb0 < 28) ? (L - rb0) : 28) : 0;
        if (t < nrows) {
            float w = expf(g_scores[rb0 + t] - M) * invS;
            s_wts[t] = w;
            attn_out[rb0 + t] = w;
        }
        __syncthreads();

        // pipelined enc tiles: 7 rows (28 KB) each, up to 4 tiles
        const int nt = (nrows + 6) / 7;
#pragma unroll
        for (int k = 0; k < DEPTH; k++) {
            if (k < nt) {
                int r0 = k * 7;
                int nr = (nrows - r0 < 7) ? (nrows - r0) : 7;
                issue_stage(slot_addr[k], enc + (size_t)(rb0 + r0) * H, nr * 256);
            } else {
                cp_commit();
            }
        }
        float acc = 0.0f;
        for (int k = 0; k < nt; k++) {
            cp_wait<DEPTH - 1>();
            __syncthreads();
            int r0 = k * 7;
            int nr = (nrows - r0 < 7) ? (nrows - r0) : 7;
            const float* sl = ring + (k % DEPTH) * SLOT_FLOATS;
#pragma unroll
            for (int r = 0; r < 7; r++)
                if (r < nr) acc += s_wts[r0 + r] * sl[r * H + t];
            __syncthreads();
            cp_commit();
        }
        cp_wait<0>();
        if (nrows > 0) atomicAdd(&g_attn[t], acc);
    }
    grid_barrier(0);

    // ===== Phase C: x = relu(comb_W @ [emb; attn] + b), pipelined ===========
    {
        s_vec[H + t] = g_attn[t];           // emb still in s_vec[0:H)
        const int tb = (b * 256) / NB, te = ((b + 1) * 256) / NB;
        const int n = te - tb;
#pragma unroll
        for (int k = 0; k < DEPTH; k++) {
            if (k < n) issue_stage(slot_addr[k], comb_W + (size_t)(tb + k) * SLOT_FLOATS, 2048);
            else       cp_commit();
        }
        for (int k = 0; k < n; k++) {
            cp_wait<DEPTH - 1>();
            __syncthreads();
            consume_dot((const float4*)(ring + (k % DEPTH) * SLOT_FLOATS),
                        (const float4*)s_vec, 2048, (tb + k) * 4, 2,
                        attn_b, comb_b, b_ih, b_hh, s_part);
            __syncthreads();
            if (k + DEPTH < n)
                issue_stage(slot_addr[k % DEPTH],
                            comb_W + (size_t)(tb + k + DEPTH) * SLOT_FLOATS, 2048);
            else
                cp_commit();
        }
        cp_wait<0>();
    }
    grid_barrier(1);

    // ===== Phase D: gates = W_ih @ x + hh + biases, pipelined ===============
    {
        s_vec[t] = g_x[t];
        const int tb = (b * 512) / NB, te = ((b + 1) * 512) / NB;
        const int n = te - tb;
#pragma unroll
        for (int k = 0; k < DEPTH; k++) {
            if (k < n) issue_stage(slot_addr[k], W_ih + (size_t)(tb + k) * SLOT_FLOATS, 2048);
            else       cp_commit();
        }
        for (int k = 0; k < n; k++) {
            cp_wait<DEPTH - 1>();
            __syncthreads();
            consume_dot((const float4*)(ring + (k % DEPTH) * SLOT_FLOATS),
                        (const float4*)s_vec, 1024, (tb + k) * 8, 3,
                        attn_b, comb_b, b_ih, b_hh, s_part);
            __syncthreads();
            if (k + DEPTH < n)
                issue_stage(slot_addr[k % DEPTH],
                            W_ih + (size_t)(tb + k + DEPTH) * SLOT_FLOATS, 2048);
            else
                cp_commit();
        }
        cp_wait<0>();
    }
    grid_barrier(0);

    // ===== Phase E: LSTM pointwise + out proj + log_softmax (block 0) =======
    if (b == 0) {
        float ig = g_gates[t];
        float fg = g_gates[H + t];
        float gg = g_gates[2 * H + t];
        float og = g_gates[3 * H + t];
        float c = sigmoidf_(fg) * c0[t] + sigmoidf_(ig) * tanhf(gg);
        float h = sigmoidf_(og) * tanhf(c);
        out[V + t] = h;
        out[V + H + t] = c;
        s_vec[t] = h;
        __syncthreads();

        const float4* hv = (const float4*)s_vec;
        if (warp < V) {
            const float4* wr = (const float4*)(out_W + (size_t)warp * H);
            float acc = 0.0f;
#pragma unroll
            for (int k = lane; k < H / 4; k += 32) acc += dot4(wr[k], hv[k]);
            acc = warp_sum(acc);
            if (lane == 0) z[warp] = acc + out_b[warp];
        }
        __syncthreads();

        if (t == 0) {
            float m = -1e30f;
            for (int r = 0; r < V; r++) m = fmaxf(m, z[r]);
            float ssum = 0.0f;
            for (int r = 0; r < V; r++) ssum += expf(z[r] - m);
            float ls = m + logf(ssum);
            for (int r = 0; r < V; r++) out[r] = z[r] - ls;
        }
    }
}

// ---------------- launch ------------------------------------------------------
extern "C" void kernel_launch(void* const* d_in, const int* in_sizes, int n_in,
                              void* d_out, int out_size) {
    const int*   tok    = (const int*)  d_in[0];
    const float* h0     = (const float*)d_in[1];
    const float* c0     = (const float*)d_in[2];
    const float* enc    = (const float*)d_in[3];
    const float* emb    = (const float*)d_in[4];
    const float* attn_W = (const float*)d_in[5];
    const float* attn_b = (const float*)d_in[6];
    const float* comb_W = (const float*)d_in[7];
    const float* comb_b = (const float*)d_in[8];
    const float* W_ih   = (const float*)d_in[9];
    const float* W_hh   = (const float*)d_in[10];
    const float* b_ih   = (const float*)d_in[11];
    const float* b_hh   = (const float*)d_in[12];
    const float* out_W  = (const float*)d_in[13];
    const float* out_b  = (const float*)d_in[14];
    float* out = (float*)d_out;

    cudaFuncSetAttribute(k_decoder, cudaFuncAttributeMaxDynamicSharedMemorySize,
                         SMEM_BYTES);
    k_decoder<<<NB, NT, SMEM_BYTES>>>(tok, h0, c0, enc, emb, attn_W, attn_b,
                                      comb_W, comb_b, W_ih, W_hh, b_ih, b_hh,
                                      out_W, out_b, out);
}